// round 8
// baseline (speedup 1.0000x reference)
#include <cuda_runtime.h>
#include <cuda_bf16.h>
#include <cstdint>

// Problem constants
#define BB 2
#define TT 4096
#define CC 512
#define HH 8
#define HD 64
#define BT (BB*TT)        // 8192
#define N_QKV (3*CC)      // 1536

// Scratch (device globals; no allocation allowed)
__device__ float g_q[BB*HH*TT*HD];   // [B,H,T,HD]
__device__ float g_k[BB*HH*TT*HD];
__device__ float g_v[BB*HH*TT*HD];
__device__ float g_y[BT*CC];         // [B*T, C] attention output

__device__ __forceinline__ uint32_t tf32c(float x) {
    uint32_t r;
    asm("cvt.rna.tf32.f32 %0, %1;" : "=r"(r) : "f"(x));
    return r;
}

__device__ __forceinline__ void mma_tf32(
    float& d0, float& d1, float& d2, float& d3,
    uint32_t a0, uint32_t a1, uint32_t a2, uint32_t a3,
    uint32_t b0, uint32_t b1)
{
    asm volatile(
        "mma.sync.aligned.m16n8k8.row.col.f32.tf32.tf32.f32 "
        "{%0,%1,%2,%3}, {%4,%5,%6,%7}, {%8,%9}, {%0,%1,%2,%3};"
        : "+f"(d0), "+f"(d1), "+f"(d2), "+f"(d3)
        : "r"(a0), "r"(a1), "r"(a2), "r"(a3), "r"(b0), "r"(b1));
}

__device__ __forceinline__ uint32_t s2u(const void* p) {
    return (uint32_t)__cvta_generic_to_shared(p);
}

// ldmatrix.x4 on tf32 data (b16 view). Lane l gets 32-bit word (row l/4,
// word l%4) of matrices M0..M3 selected by lane groups 0-7/8-15/16-23/24-31.
__device__ __forceinline__ void ldsm4(uint32_t& r0, uint32_t& r1,
                                      uint32_t& r2, uint32_t& r3, uint32_t a)
{
    asm volatile("ldmatrix.sync.aligned.m8n8.x4.shared.b16 {%0,%1,%2,%3}, [%4];"
        : "=r"(r0), "=r"(r1), "=r"(r2), "=r"(r3) : "r"(a));
}

// ---------------------------------------------------------------------------
// tf32 GEMM: out[M=8192, NN] = A[8192,512] @ W[512,NN] + bias.
// As: [m][k] row-major stride GPAD. Bs: TRANSPOSED [n][k] stride GPAD so
// b-frags come from ldmatrix (b0=B[k=lam][n=g] <- mem rows n, words k).
// Per k8-step: 1 ldmatrix.x4 (A) + 4 ldmatrix.x4 (B, 2 n-tiles each).
// ---------------------------------------------------------------------------
#define GPAD 68

template<int NN, bool SCATTER, bool A_IS_Y>
__global__ __launch_bounds__(128) void gemm_tf32_kernel(
    const float* __restrict__ A_arg, const float* __restrict__ W,
    const float* __restrict__ bias, float* __restrict__ out)
{
    __shared__ __align__(16) float As[64 * GPAD];
    __shared__ __align__(16) float Bs[64 * GPAD];

    const float* __restrict__ A = A_IS_Y ? (const float*)g_y : A_arg;

    const int tid = threadIdx.x;
    const int w = tid >> 5;
    const int lane = tid & 31;
    const int g = lane >> 2;
    const int lam = lane & 3;

    const int bn = blockIdx.x * 64;
    const int bm = blockIdx.y * 64;

    // ldmatrix per-lane base addresses (bytes)
    const int arow = w * 16 + (lane & 15);
    const uint32_t As_base = s2u(As) + (uint32_t)(arow * GPAD + ((lane >> 4) << 2)) * 4u;
    const int brow = (lane & 7) + ((lane & 16) ? 8 : 0);
    const uint32_t Bs_base = s2u(Bs) + (uint32_t)(brow * GPAD + (((lane >> 3) & 1) << 2)) * 4u;

    float sacc[8][4];
    #pragma unroll
    for (int n = 0; n < 8; n++)
        #pragma unroll
        for (int i = 0; i < 4; i++) sacc[n][i] = 0.f;

    for (int k0 = 0; k0 < CC; k0 += 64) {
        __syncthreads();
        #pragma unroll
        for (int i = 0; i < 8; i++) {
            int f = tid + i * 128;           // 0..1023
            int r = f >> 4;
            int c4 = (f & 15) * 4;
            float4 av = *(const float4*)(A + (size_t)(bm + r) * CC + k0 + c4);
            float4 bv = *(const float4*)(W + (size_t)(k0 + r) * NN + bn + c4);
            uint32_t* ad = (uint32_t*)&As[r * GPAD + c4];
            ad[0] = tf32c(av.x); ad[1] = tf32c(av.y);
            ad[2] = tf32c(av.z); ad[3] = tf32c(av.w);
            // B transposed: Bs[n][k] = W[k][n]
            Bs[(c4 + 0) * GPAD + r] = __uint_as_float(tf32c(bv.x));
            Bs[(c4 + 1) * GPAD + r] = __uint_as_float(tf32c(bv.y));
            Bs[(c4 + 2) * GPAD + r] = __uint_as_float(tf32c(bv.z));
            Bs[(c4 + 3) * GPAD + r] = __uint_as_float(tf32c(bv.w));
        }
        __syncthreads();

        #pragma unroll
        for (int ks = 0; ks < 8; ks++) {
            uint32_t a0, a1, a2, a3;
            ldsm4(a0, a1, a2, a3, As_base + ks * 32);
            #pragma unroll
            for (int np = 0; np < 4; np++) {
                uint32_t b0, b1, b2, b3;
                ldsm4(b0, b1, b2, b3, Bs_base + np * (16 * GPAD * 4) + ks * 32);
                mma_tf32(sacc[2*np][0], sacc[2*np][1], sacc[2*np][2], sacc[2*np][3],
                         a0, a1, a2, a3, b0, b1);
                mma_tf32(sacc[2*np+1][0], sacc[2*np+1][1], sacc[2*np+1][2], sacc[2*np+1][3],
                         a0, a1, a2, a3, b2, b3);
            }
        }
    }

    // Epilogue
    const int m0 = bm + w * 16 + g;
    const int m1 = m0 + 8;
    #pragma unroll
    for (int n = 0; n < 8; n++) {
        #pragma unroll
        for (int p = 0; p < 2; p++) {
            int col = bn + n * 8 + 2 * lam + p;
            float bsv = bias[col];
            float v0 = sacc[n][0 + p] + bsv;
            float v1 = sacc[n][2 + p] + bsv;
            if (SCATTER) {
                int which = col / CC;
                int c = col % CC;
                int h = c >> 6;
                int d = c & 63;
                float* dst = (which == 0) ? g_q : (which == 1) ? g_k : g_v;
                size_t base = (((size_t)(m0 >> 12) * HH + h) * TT) * HD + d;
                dst[base + (size_t)(m0 & 4095) * HD] = v0;
                dst[base + (size_t)(m1 & 4095) * HD] = v1;
            } else {
                out[(size_t)m0 * NN + col] = v0;
                out[(size_t)m1 * NN + col] = v1;
            }
        }
    }
}

// ---------------------------------------------------------------------------
// Flash attention, tf32 mma + ldmatrix fragment loads.
// Ks [key][d] (natural == [n][k] for S pass). Vt [d][key] (transposed,
// == [n][k] for PV pass). Ps [row][k] row-major for a-frags.
// ---------------------------------------------------------------------------
#define QT 64
#define KTL 64
#define PADS 68

__global__ __launch_bounds__(128) void attn_kernel()
{
    extern __shared__ __align__(16) float smem[];
    float* Ks = smem;                 // [64][PADS]  rows=key, words=d
    float* Vt = smem + KTL * PADS;    // [64][PADS]  rows=d,   words=key
    float* Ps = smem + 2 * KTL * PADS;// [64][PADS]  rows=q,   words=key

    const int tid = threadIdx.x;
    const int w = tid >> 5;
    const int lane = tid & 31;
    const int g = lane >> 2;
    const int lam = lane & 3;

    const int b = blockIdx.z;
    const int h = blockIdx.y;
    const int qt = (gridDim.x - 1) - blockIdx.x;   // heavy tiles first
    const int q0 = qt * QT;

    const size_t head_off = ((size_t)b * HH + h) * TT * HD;
    const float* kbase = g_k + head_off;
    const float* vbase = g_v + head_off;

    const int qi0 = q0 + w * 16 + g;
    const int qi1 = qi0 + 8;

    // ldmatrix per-lane base addresses
    const int arow = w * 16 + (lane & 15);
    const uint32_t Ps_base = s2u(Ps) + (uint32_t)(arow * PADS + ((lane >> 4) << 2)) * 4u;
    const int brow = (lane & 7) + ((lane & 16) ? 8 : 0);
    const uint32_t Ks_base = s2u(Ks) + (uint32_t)(brow * PADS + (((lane >> 3) & 1) << 2)) * 4u;
    const uint32_t Vt_base = s2u(Vt) + (uint32_t)(brow * PADS + (((lane >> 3) & 1) << 2)) * 4u;

    uint32_t qa[8][4];
    {
        const float* qr0 = g_q + head_off + (size_t)qi0 * HD;
        const float* qr1 = g_q + head_off + (size_t)qi1 * HD;
        #pragma unroll
        for (int ks = 0; ks < 8; ks++) {
            qa[ks][0] = tf32c(qr0[ks * 8 + lam] * 0.125f);
            qa[ks][1] = tf32c(qr1[ks * 8 + lam] * 0.125f);
            qa[ks][2] = tf32c(qr0[ks * 8 + lam + 4] * 0.125f);
            qa[ks][3] = tf32c(qr1[ks * 8 + lam + 4] * 0.125f);
        }
    }

    float oacc[8][4];
    #pragma unroll
    for (int n = 0; n < 8; n++)
        #pragma unroll
        for (int i = 0; i < 4; i++) oacc[n][i] = 0.f;
    float m0 = -1e30f, m1 = -1e30f, l0 = 0.f, l1 = 0.f;

    const int ktiles = qt + 1;

    for (int kt = 0; kt < ktiles; kt++) {
        __syncthreads();
        {
            const float4* ksrc = (const float4*)(kbase + (size_t)kt * KTL * HD);
            const float4* vsrc = (const float4*)(vbase + (size_t)kt * KTL * HD);
            #pragma unroll
            for (int i = 0; i < 8; i++) {
                int f = tid + i * 128;
                int r = f >> 4;                 // key index
                int c4 = (f & 15) * 4;          // d offset
                float4 kv = ksrc[f];
                float4 vv = vsrc[f];
                uint32_t* kd = (uint32_t*)&Ks[r * PADS + c4];
                kd[0] = tf32c(kv.x); kd[1] = tf32c(kv.y);
                kd[2] = tf32c(kv.z); kd[3] = tf32c(kv.w);
                // V transposed: Vt[d][key]
                Vt[(c4 + 0) * PADS + r] = __uint_as_float(tf32c(vv.x));
                Vt[(c4 + 1) * PADS + r] = __uint_as_float(tf32c(vv.y));
                Vt[(c4 + 2) * PADS + r] = __uint_as_float(tf32c(vv.z));
                Vt[(c4 + 3) * PADS + r] = __uint_as_float(tf32c(vv.w));
            }
        }
        __syncthreads();

        float sacc[8][4];
        #pragma unroll
        for (int n = 0; n < 8; n++)
            #pragma unroll
            for (int i = 0; i < 4; i++) sacc[n][i] = 0.f;

        #pragma unroll
        for (int ks = 0; ks < 8; ks++) {
            #pragma unroll
            for (int np = 0; np < 4; np++) {
                uint32_t b0, b1, b2, b3;
                ldsm4(b0, b1, b2, b3, Ks_base + np * (16 * PADS * 4) + ks * 32);
                mma_tf32(sacc[2*np][0], sacc[2*np][1], sacc[2*np][2], sacc[2*np][3],
                         qa[ks][0], qa[ks][1], qa[ks][2], qa[ks][3], b0, b1);
                mma_tf32(sacc[2*np+1][0], sacc[2*np+1][1], sacc[2*np+1][2], sacc[2*np+1][3],
                         qa[ks][0], qa[ks][1], qa[ks][2], qa[ks][3], b2, b3);
            }
        }

        if (kt == qt) {
            #pragma unroll
            for (int n = 0; n < 8; n++) {
                int jg = kt * KTL + n * 8 + 2 * lam;
                if (jg > qi0)     sacc[n][0] = -1e30f;
                if (jg + 1 > qi0) sacc[n][1] = -1e30f;
                if (jg > qi1)     sacc[n][2] = -1e30f;
                if (jg + 1 > qi1) sacc[n][3] = -1e30f;
            }
        }

        float mx0 = -1e30f, mx1 = -1e30f;
        #pragma unroll
        for (int n = 0; n < 8; n++) {
            mx0 = fmaxf(mx0, fmaxf(sacc[n][0], sacc[n][1]));
            mx1 = fmaxf(mx1, fmaxf(sacc[n][2], sacc[n][3]));
        }
        mx0 = fmaxf(mx0, __shfl_xor_sync(0xffffffff, mx0, 1));
        mx0 = fmaxf(mx0, __shfl_xor_sync(0xffffffff, mx0, 2));
        mx1 = fmaxf(mx1, __shfl_xor_sync(0xffffffff, mx1, 1));
        mx1 = fmaxf(mx1, __shfl_xor_sync(0xffffffff, mx1, 2));

        float m0n = fmaxf(m0, mx0);
        float m1n = fmaxf(m1, mx1);
        float al0 = __expf(m0 - m0n);
        float al1 = __expf(m1 - m1n);
        m0 = m0n; m1 = m1n;

        #pragma unroll
        for (int n = 0; n < 8; n++) {
            oacc[n][0] *= al0; oacc[n][1] *= al0;
            oacc[n][2] *= al1; oacc[n][3] *= al1;
        }

        float rs0 = 0.f, rs1 = 0.f;
        #pragma unroll
        for (int n = 0; n < 8; n++) {
            float p0 = __expf(sacc[n][0] - m0);
            float p1 = __expf(sacc[n][1] - m0);
            float p2 = __expf(sacc[n][2] - m1);
            float p3 = __expf(sacc[n][3] - m1);
            rs0 += p0 + p1;
            rs1 += p2 + p3;
            uint2* d0 = (uint2*)&Ps[(w * 16 + g) * PADS + n * 8 + 2 * lam];
            uint2* d1 = (uint2*)&Ps[(w * 16 + g + 8) * PADS + n * 8 + 2 * lam];
            *d0 = make_uint2(tf32c(p0), tf32c(p1));
            *d1 = make_uint2(tf32c(p2), tf32c(p3));
        }
        rs0 += __shfl_xor_sync(0xffffffff, rs0, 1);
        rs0 += __shfl_xor_sync(0xffffffff, rs0, 2);
        rs1 += __shfl_xor_sync(0xffffffff, rs1, 1);
        rs1 += __shfl_xor_sync(0xffffffff, rs1, 2);
        l0 = l0 * al0 + rs0;
        l1 = l1 * al1 + rs1;

        __syncwarp();

        #pragma unroll
        for (int ks = 0; ks < 8; ks++) {
            uint32_t a0, a1, a2, a3;
            ldsm4(a0, a1, a2, a3, Ps_base + ks * 32);
            #pragma unroll
            for (int np = 0; np < 4; np++) {
                uint32_t b0, b1, b2, b3;
                ldsm4(b0, b1, b2, b3, Vt_base + np * (16 * PADS * 4) + ks * 32);
                mma_tf32(oacc[2*np][0], oacc[2*np][1], oacc[2*np][2], oacc[2*np][3],
                         a0, a1, a2, a3, b0, b1);
                mma_tf32(oacc[2*np+1][0], oacc[2*np+1][1], oacc[2*np+1][2], oacc[2*np+1][3],
                         a0, a1, a2, a3, b2, b3);
            }
        }
        __syncwarp();
    }

    const float inv0 = 1.f / l0;
    const float inv1 = 1.f / l1;
    float* y0 = g_y + ((size_t)b * TT + qi0) * CC + h * HD;
    float* y1 = g_y + ((size_t)b * TT + qi1) * CC + h * HD;
    #pragma unroll
    for (int n = 0; n < 8; n++) {
        int c = n * 8 + 2 * lam;
        *(float2*)&y0[c] = make_float2(oacc[n][0] * inv0, oacc[n][1] * inv0);
        *(float2*)&y1[c] = make_float2(oacc[n][2] * inv1, oacc[n][3] * inv1);
    }
}

// ---------------------------------------------------------------------------
extern "C" void kernel_launch(void* const* d_in, const int* in_sizes, int n_in,
                              void* d_out, int out_size)
{
    (void)in_sizes; (void)n_in; (void)out_size;
    const float* x     = (const float*)d_in[0];
    const float* Wqkv  = (const float*)d_in[1];
    const float* bqkv  = (const float*)d_in[2];
    const float* Wproj = (const float*)d_in[3];
    const float* bproj = (const float*)d_in[4];
    float* out = (float*)d_out;

    static int smem_set = 0;
    const int attn_smem = 3 * KTL * PADS * (int)sizeof(float);  // 52224
    if (!smem_set) {
        cudaFuncSetAttribute(attn_kernel,
                             cudaFuncAttributeMaxDynamicSharedMemorySize,
                             attn_smem);
        smem_set = 1;
    }

    dim3 g1(N_QKV / 64, BT / 64);
    gemm_tf32_kernel<N_QKV, true, false><<<g1, 128>>>(x, Wqkv, bqkv, nullptr);

    dim3 g2(TT / QT, HH, BB);
    attn_kernel<<<g2, 128, attn_smem>>>();

    dim3 g3(CC / 64, BT / 64);
    gemm_tf32_kernel<CC, false, true><<<g3, 128>>>(nullptr, Wproj, bproj, out);
}

// round 9
// speedup vs baseline: 1.2499x; 1.2499x over previous
#include <cuda_runtime.h>
#include <cuda_bf16.h>
#include <cstdint>

// Problem constants
#define BB 2
#define TT 4096
#define CC 512
#define HH 8
#define HD 64
#define BT (BB*TT)        // 8192
#define N_QKV (3*CC)      // 1536

// Scratch (device globals; no allocation allowed)
__device__ float g_q[BB*HH*TT*HD];   // [B,H,T,HD]
__device__ float g_k[BB*HH*TT*HD];
__device__ float g_v[BB*HH*TT*HD];
__device__ float g_y[BT*CC];         // [B*T, C] attention output

__device__ __forceinline__ uint32_t tf32c(float x) {
    uint32_t r;
    asm("cvt.rna.tf32.f32 %0, %1;" : "=r"(r) : "f"(x));
    return r;
}

__device__ __forceinline__ void mma_tf32(
    float& d0, float& d1, float& d2, float& d3,
    uint32_t a0, uint32_t a1, uint32_t a2, uint32_t a3,
    uint32_t b0, uint32_t b1)
{
    asm volatile(
        "mma.sync.aligned.m16n8k8.row.col.f32.tf32.tf32.f32 "
        "{%0,%1,%2,%3}, {%4,%5,%6,%7}, {%8,%9}, {%0,%1,%2,%3};"
        : "+f"(d0), "+f"(d1), "+f"(d2), "+f"(d3)
        : "r"(a0), "r"(a1), "r"(a2), "r"(a3), "r"(b0), "r"(b1));
}

__device__ __forceinline__ uint32_t s2u(const void* p) {
    return (uint32_t)__cvta_generic_to_shared(p);
}

__device__ __forceinline__ void ldsm4(uint32_t& r0, uint32_t& r1,
                                      uint32_t& r2, uint32_t& r3, uint32_t a)
{
    asm volatile("ldmatrix.sync.aligned.m8n8.x4.shared.b16 {%0,%1,%2,%3}, [%4];"
        : "=r"(r0), "=r"(r1), "=r"(r2), "=r"(r3) : "r"(a));
}

// ---------------------------------------------------------------------------
// tf32 GEMM: out[M=8192, NN] = A[8192,512] @ W[512,NN] + bias.
// BM=128, BN=64, BK=64, 128 threads (4 warps), warp tile 32x64 (two m16
// tiles share every b-fragment: 1.5 smem wavefronts per mma).
// As [m][k] row-major stride 68; Bs TRANSPOSED [n][k] stride 68 staged
// conflict-free: per-thread k-vectorized gmem loads + STS.128 row store
// (bank = 4n + k_base, distinct across each 8-lane phase).
// ---------------------------------------------------------------------------
#define GPAD 68
#define GSMEM ((128 + 64) * GPAD * 4)   // 52224 bytes

template<int NN, bool SCATTER, bool A_IS_Y>
__global__ __launch_bounds__(128) void gemm_tf32_kernel(
    const float* __restrict__ A_arg, const float* __restrict__ W,
    const float* __restrict__ bias, float* __restrict__ out)
{
    extern __shared__ __align__(16) float gsm[];
    float* As = gsm;                 // [128][GPAD]
    float* Bs = gsm + 128 * GPAD;    // [64][GPAD]  (n-major, k words)

    const float* __restrict__ A = A_IS_Y ? (const float*)g_y : A_arg;

    const int tid = threadIdx.x;
    const int w = tid >> 5;
    const int lane = tid & 31;
    const int g = lane >> 2;
    const int lam = lane & 3;

    const int bn = blockIdx.x * 64;
    const int bm = blockIdx.y * 128;

    // ldmatrix per-lane base addresses (bytes)
    const int arow = w * 32 + (lane & 15);
    const uint32_t As_base0 = s2u(As) + (uint32_t)(arow * GPAD + ((lane >> 4) << 2)) * 4u;
    const uint32_t As_base1 = As_base0 + 16u * GPAD * 4u;
    const int brow = (lane & 7) + ((lane & 16) ? 8 : 0);
    const uint32_t Bs_base = s2u(Bs) + (uint32_t)(brow * GPAD + (((lane >> 3) & 1) << 2)) * 4u;

    // B staging coords: thread owns column n, 32 k values (8 x float4)
    const int sn = tid & 63;
    const int skq = (tid >> 6) * 32;

    float sacc[2][8][4];
    #pragma unroll
    for (int mt = 0; mt < 2; mt++)
        #pragma unroll
        for (int n = 0; n < 8; n++)
            #pragma unroll
            for (int i = 0; i < 4; i++) sacc[mt][n][i] = 0.f;

    for (int k0 = 0; k0 < CC; k0 += 64) {
        __syncthreads();
        // Stage A tile 128x64 (row-major)
        #pragma unroll
        for (int i = 0; i < 16; i++) {
            int f = tid + i * 128;           // 0..2047
            int r = f >> 4;
            int c4 = (f & 15) * 4;
            float4 av = *(const float4*)(A + (size_t)(bm + r) * CC + k0 + c4);
            uint4 at;
            at.x = tf32c(av.x); at.y = tf32c(av.y);
            at.z = tf32c(av.z); at.w = tf32c(av.w);
            *(uint4*)&As[r * GPAD + c4] = at;
        }
        // Stage B tile 64x64 transposed [n][k]: k-vectorized, conflict-free
        #pragma unroll
        for (int i = 0; i < 8; i++) {
            int kb = skq + i * 4;
            uint4 bt;
            bt.x = tf32c(W[(size_t)(k0 + kb + 0) * NN + bn + sn]);
            bt.y = tf32c(W[(size_t)(k0 + kb + 1) * NN + bn + sn]);
            bt.z = tf32c(W[(size_t)(k0 + kb + 2) * NN + bn + sn]);
            bt.w = tf32c(W[(size_t)(k0 + kb + 3) * NN + bn + sn]);
            *(uint4*)&Bs[sn * GPAD + kb] = bt;
        }
        __syncthreads();

        #pragma unroll
        for (int ks = 0; ks < 8; ks++) {
            uint32_t a00, a01, a02, a03, a10, a11, a12, a13;
            ldsm4(a00, a01, a02, a03, As_base0 + ks * 32);
            ldsm4(a10, a11, a12, a13, As_base1 + ks * 32);
            #pragma unroll
            for (int np = 0; np < 4; np++) {
                uint32_t b0, b1, b2, b3;
                ldsm4(b0, b1, b2, b3, Bs_base + np * (16 * GPAD * 4) + ks * 32);
                mma_tf32(sacc[0][2*np][0], sacc[0][2*np][1], sacc[0][2*np][2], sacc[0][2*np][3],
                         a00, a01, a02, a03, b0, b1);
                mma_tf32(sacc[0][2*np+1][0], sacc[0][2*np+1][1], sacc[0][2*np+1][2], sacc[0][2*np+1][3],
                         a00, a01, a02, a03, b2, b3);
                mma_tf32(sacc[1][2*np][0], sacc[1][2*np][1], sacc[1][2*np][2], sacc[1][2*np][3],
                         a10, a11, a12, a13, b0, b1);
                mma_tf32(sacc[1][2*np+1][0], sacc[1][2*np+1][1], sacc[1][2*np+1][2], sacc[1][2*np+1][3],
                         a10, a11, a12, a13, b2, b3);
            }
        }
    }

    // Epilogue
    #pragma unroll
    for (int mt = 0; mt < 2; mt++) {
        const int m0 = bm + w * 32 + mt * 16 + g;
        const int m1 = m0 + 8;
        #pragma unroll
        for (int n = 0; n < 8; n++) {
            #pragma unroll
            for (int p = 0; p < 2; p++) {
                int col = bn + n * 8 + 2 * lam + p;
                float bsv = bias[col];
                float v0 = sacc[mt][n][0 + p] + bsv;
                float v1 = sacc[mt][n][2 + p] + bsv;
                if (SCATTER) {
                    int which = col / CC;
                    int c = col % CC;
                    int h = c >> 6;
                    int d = c & 63;
                    float* dst = (which == 0) ? g_q : (which == 1) ? g_k : g_v;
                    size_t base = (((size_t)(m0 >> 12) * HH + h) * TT) * HD + d;
                    dst[base + (size_t)(m0 & 4095) * HD] = v0;
                    dst[base + (size_t)(m1 & 4095) * HD] = v1;
                } else {
                    out[(size_t)m0 * NN + col] = v0;
                    out[(size_t)m1 * NN + col] = v1;
                }
            }
        }
    }
}

// ---------------------------------------------------------------------------
// Flash attention with tf32 mma.sync.m16n8k8 — exact R7 version (known-good
// 455us; scalar fragment loads, natural K/V layouts).
// ---------------------------------------------------------------------------
#define QT 64
#define KTL 64
#define PADS 68

__global__ __launch_bounds__(128) void attn_kernel()
{
    extern __shared__ float smem[];
    float* Ks = smem;                 // [64][PADS]
    float* Vs = smem + KTL * PADS;    // [64][PADS]
    float* Ps = smem + 2 * KTL * PADS;// [64][PADS]

    const int tid = threadIdx.x;
    const int w = tid >> 5;
    const int lane = tid & 31;
    const int g = lane >> 2;
    const int lam = lane & 3;

    const int b = blockIdx.z;
    const int h = blockIdx.y;
    const int qt = (gridDim.x - 1) - blockIdx.x;   // heavy tiles first
    const int q0 = qt * QT;

    const size_t head_off = ((size_t)b * HH + h) * TT * HD;
    const float* kbase = g_k + head_off;
    const float* vbase = g_v + head_off;

    const int qi0 = q0 + w * 16 + g;
    const int qi1 = qi0 + 8;

    uint32_t qa[8][4];
    {
        const float* qr0 = g_q + head_off + (size_t)qi0 * HD;
        const float* qr1 = g_q + head_off + (size_t)qi1 * HD;
        #pragma unroll
        for (int ks = 0; ks < 8; ks++) {
            qa[ks][0] = tf32c(qr0[ks * 8 + lam] * 0.125f);
            qa[ks][1] = tf32c(qr1[ks * 8 + lam] * 0.125f);
            qa[ks][2] = tf32c(qr0[ks * 8 + lam + 4] * 0.125f);
            qa[ks][3] = tf32c(qr1[ks * 8 + lam + 4] * 0.125f);
        }
    }

    float oacc[8][4];
    #pragma unroll
    for (int n = 0; n < 8; n++)
        #pragma unroll
        for (int i = 0; i < 4; i++) oacc[n][i] = 0.f;
    float m0 = -1e30f, m1 = -1e30f, l0 = 0.f, l1 = 0.f;

    const int ktiles = qt + 1;

    for (int kt = 0; kt < ktiles; kt++) {
        __syncthreads();
        {
            const float4* ksrc = (const float4*)(kbase + (size_t)kt * KTL * HD);
            const float4* vsrc = (const float4*)(vbase + (size_t)kt * KTL * HD);
            #pragma unroll
            for (int i = 0; i < 8; i++) {
                int f = tid + i * 128;
                int r = f >> 4;
                int c4 = (f & 15) * 4;
                float4 kv = ksrc[f];
                float4 vv = vsrc[f];
                uint32_t* kd = (uint32_t*)&Ks[r * PADS + c4];
                uint32_t* vd = (uint32_t*)&Vs[r * PADS + c4];
                kd[0] = tf32c(kv.x); kd[1] = tf32c(kv.y);
                kd[2] = tf32c(kv.z); kd[3] = tf32c(kv.w);
                vd[0] = tf32c(vv.x); vd[1] = tf32c(vv.y);
                vd[2] = tf32c(vv.z); vd[3] = tf32c(vv.w);
            }
        }
        __syncthreads();

        float sacc[8][4];
        #pragma unroll
        for (int n = 0; n < 8; n++)
            #pragma unroll
            for (int i = 0; i < 4; i++) sacc[n][i] = 0.f;

        #pragma unroll
        for (int ks = 0; ks < 8; ks++) {
            #pragma unroll
            for (int n = 0; n < 8; n++) {
                uint32_t b0 = __float_as_uint(Ks[(n * 8 + g) * PADS + ks * 8 + lam]);
                uint32_t b1 = __float_as_uint(Ks[(n * 8 + g) * PADS + ks * 8 + lam + 4]);
                mma_tf32(sacc[n][0], sacc[n][1], sacc[n][2], sacc[n][3],
                         qa[ks][0], qa[ks][1], qa[ks][2], qa[ks][3], b0, b1);
            }
        }

        if (kt == qt) {
            #pragma unroll
            for (int n = 0; n < 8; n++) {
                int jg = kt * KTL + n * 8 + 2 * lam;
                if (jg > qi0)     sacc[n][0] = -1e30f;
                if (jg + 1 > qi0) sacc[n][1] = -1e30f;
                if (jg > qi1)     sacc[n][2] = -1e30f;
                if (jg + 1 > qi1) sacc[n][3] = -1e30f;
            }
        }

        float mx0 = -1e30f, mx1 = -1e30f;
        #pragma unroll
        for (int n = 0; n < 8; n++) {
            mx0 = fmaxf(mx0, fmaxf(sacc[n][0], sacc[n][1]));
            mx1 = fmaxf(mx1, fmaxf(sacc[n][2], sacc[n][3]));
        }
        mx0 = fmaxf(mx0, __shfl_xor_sync(0xffffffff, mx0, 1));
        mx0 = fmaxf(mx0, __shfl_xor_sync(0xffffffff, mx0, 2));
        mx1 = fmaxf(mx1, __shfl_xor_sync(0xffffffff, mx1, 1));
        mx1 = fmaxf(mx1, __shfl_xor_sync(0xffffffff, mx1, 2));

        float m0n = fmaxf(m0, mx0);
        float m1n = fmaxf(m1, mx1);
        float al0 = __expf(m0 - m0n);
        float al1 = __expf(m1 - m1n);
        m0 = m0n; m1 = m1n;

        #pragma unroll
        for (int n = 0; n < 8; n++) {
            oacc[n][0] *= al0; oacc[n][1] *= al0;
            oacc[n][2] *= al1; oacc[n][3] *= al1;
        }

        float rs0 = 0.f, rs1 = 0.f;
        #pragma unroll
        for (int n = 0; n < 8; n++) {
            float p0 = __expf(sacc[n][0] - m0);
            float p1 = __expf(sacc[n][1] - m0);
            float p2 = __expf(sacc[n][2] - m1);
            float p3 = __expf(sacc[n][3] - m1);
            rs0 += p0 + p1;
            rs1 += p2 + p3;
            uint2* d0 = (uint2*)&Ps[(w * 16 + g) * PADS + n * 8 + 2 * lam];
            uint2* d1 = (uint2*)&Ps[(w * 16 + g + 8) * PADS + n * 8 + 2 * lam];
            *d0 = make_uint2(tf32c(p0), tf32c(p1));
            *d1 = make_uint2(tf32c(p2), tf32c(p3));
        }
        rs0 += __shfl_xor_sync(0xffffffff, rs0, 1);
        rs0 += __shfl_xor_sync(0xffffffff, rs0, 2);
        rs1 += __shfl_xor_sync(0xffffffff, rs1, 1);
        rs1 += __shfl_xor_sync(0xffffffff, rs1, 2);
        l0 = l0 * al0 + rs0;
        l1 = l1 * al1 + rs1;

        __syncwarp();

        #pragma unroll
        for (int ks = 0; ks < 8; ks++) {
            uint32_t a0 = __float_as_uint(Ps[(w * 16 + g) * PADS + ks * 8 + lam]);
            uint32_t a1 = __float_as_uint(Ps[(w * 16 + g + 8) * PADS + ks * 8 + lam]);
            uint32_t a2 = __float_as_uint(Ps[(w * 16 + g) * PADS + ks * 8 + lam + 4]);
            uint32_t a3 = __float_as_uint(Ps[(w * 16 + g + 8) * PADS + ks * 8 + lam + 4]);
            #pragma unroll
            for (int n = 0; n < 8; n++) {
                uint32_t b0 = __float_as_uint(Vs[(ks * 8 + lam) * PADS + n * 8 + g]);
                uint32_t b1 = __float_as_uint(Vs[(ks * 8 + lam + 4) * PADS + n * 8 + g]);
                mma_tf32(oacc[n][0], oacc[n][1], oacc[n][2], oacc[n][3],
                         a0, a1, a2, a3, b0, b1);
            }
        }
        __syncwarp();
    }

    const float inv0 = 1.f / l0;
    const float inv1 = 1.f / l1;
    float* y0 = g_y + ((size_t)b * TT + qi0) * CC + h * HD;
    float* y1 = g_y + ((size_t)b * TT + qi1) * CC + h * HD;
    #pragma unroll
    for (int n = 0; n < 8; n++) {
        int c = n * 8 + 2 * lam;
        *(float2*)&y0[c] = make_float2(oacc[n][0] * inv0, oacc[n][1] * inv0);
        *(float2*)&y1[c] = make_float2(oacc[n][2] * inv1, oacc[n][3] * inv1);
    }
}

// ---------------------------------------------------------------------------
extern "C" void kernel_launch(void* const* d_in, const int* in_sizes, int n_in,
                              void* d_out, int out_size)
{
    (void)in_sizes; (void)n_in; (void)out_size;
    const float* x     = (const float*)d_in[0];
    const float* Wqkv  = (const float*)d_in[1];
    const float* bqkv  = (const float*)d_in[2];
    const float* Wproj = (const float*)d_in[3];
    const float* bproj = (const float*)d_in[4];
    float* out = (float*)d_out;

    static int smem_set = 0;
    const int attn_smem = 3 * KTL * PADS * (int)sizeof(float);  // 52224
    if (!smem_set) {
        cudaFuncSetAttribute(attn_kernel,
                             cudaFuncAttributeMaxDynamicSharedMemorySize,
                             attn_smem);
        cudaFuncSetAttribute(gemm_tf32_kernel<N_QKV, true, false>,
                             cudaFuncAttributeMaxDynamicSharedMemorySize,
                             GSMEM);
        cudaFuncSetAttribute(gemm_tf32_kernel<CC, false, true>,
                             cudaFuncAttributeMaxDynamicSharedMemorySize,
                             GSMEM);
        smem_set = 1;
    }

    dim3 g1(N_QKV / 64, BT / 128);
    gemm_tf32_kernel<N_QKV, true, false><<<g1, 128, GSMEM>>>(x, Wqkv, bqkv, nullptr);

    dim3 g2(TT / QT, HH, BB);
    attn_kernel<<<g2, 128, attn_smem>>>();

    dim3 g3(CC / 64, BT / 128);
    gemm_tf32_kernel<CC, false, true><<<g3, 128, GSMEM>>>(nullptr, Wproj, bproj, out);
}